// round 15
// baseline (speedup 1.0000x reference)
#include <cuda_runtime.h>
#include <cuda_bf16.h>
#include <cstdint>

#define N_NODES   50000
#define N_EDGES   1600000
#define F_IN      128
#define F_OUT     8
#define K_TAPS    4
#define MAX_POWER 25            // F_OUT*(K_TAPS-1)+1

#define CHUNKS    4
#define CHUNK_N   (N_NODES / CHUNKS)        // 12500 nodes per column chunk
#define NKEYS     (N_NODES * CHUNKS)        // 200000 (row, chunk) keys
#define CF4       (N_NODES / 4 / CHUNKS)    // 3125 float4 per chunk copy

#define GRID_P    148           // persistent grid: 1 CTA/SM, all co-resident
#define T_P       1024
#define ROWS_PER_CTA ((N_NODES + GRID_P - 1) / GRID_P)   // 338
#define SMEM_BYTES (N_NODES * 4)                          // 200 KB dynamic

// ---- device-global scratch ----
__device__ __align__(16) float g_s[(MAX_POWER + 1) * N_NODES];  // 5.2 MB
__device__ int      g_cnt[NKEYS];
__device__ int      g_rowptr[NKEYS + 1];
__device__ int      g_fill[NKEYS];
__device__ int2     g_csr[N_EDGES];                   // packed {col, val-bits}
__device__ int      g_part[GRID_P];                   // per-CTA edge-count partials
__device__ unsigned g_arrive;                         // barrier arrivals (monotonic)
__device__ unsigned g_epoch;                          // completed-epoch counter
__device__ unsigned g_done;                           // end-of-kernel reset counter

// ---------------------------------------------------------------------------
// cp.async helpers (LDGSTS): 16B global->shared, fire-and-forget.
// ---------------------------------------------------------------------------
__device__ __forceinline__ void cp_async16(unsigned int dst_smem, const float4* src) {
    asm volatile("cp.async.cg.shared.global [%0], [%1], 16;"
                 :: "r"(dst_smem), "l"(src));
}
__device__ __forceinline__ void cp_commit() {
    asm volatile("cp.async.commit_group;");
}
#define CP_WAIT_GROUP(N) asm volatile("cp.async.wait_group %0;" :: "n"(N))

// ---------------------------------------------------------------------------
// Device-wide barrier: one atomic arrive per CTA; LAST arriver publishes the
// epoch; everyone else spins on a PLAIN LOAD with nanosleep backoff
// (no RMW serialization in the spin path).
// ---------------------------------------------------------------------------
__device__ __forceinline__ void grid_barrier(unsigned target) {
    __syncthreads();
    if (threadIdx.x == 0) {
        __threadfence();                               // release this CTA's writes
        unsigned arrived = atomicAdd(&g_arrive, 1u) + 1u;
        if (arrived == target * GRID_P) {
            __threadfence();
            *(volatile unsigned*)&g_epoch = target;    // publish epoch
        } else {
            while (*(volatile unsigned*)&g_epoch < target) __nanosleep(32);
        }
        __threadfence();                               // acquire
    }
    __syncthreads();
}

// ---------------------------------------------------------------------------
// ONE fused persistent kernel: chunked-CSR build + rowsum + 25 pipelined
// power iterations + output. smem holds the whole power vector (200 KB).
// ---------------------------------------------------------------------------
__global__ void __launch_bounds__(T_P, 1)
gfl_fused_kernel(const float* __restrict__ x,
                 const int*   __restrict__ rows,
                 const int*   __restrict__ cols,
                 const float* __restrict__ vals,
                 const float* __restrict__ coeff,
                 float*       __restrict__ y) {
    extern __shared__ float sv[];                 // N_NODES floats (dynamic)
    __shared__ int   scanbuf[T_P];
    __shared__ float racc[ROWS_PER_CTA];
    __shared__ int   s_base;

    const int tid  = threadIdx.x;
    const int wid  = tid >> 5;
    const int lane = tid & 31;
    const int sub  = lane >> 3;                   // 8-lane sub-group 0..3
    const int sl   = lane & 7;
    const unsigned submask = 0xFFu << (sub * 8);
    const int cta  = blockIdx.x;

    const int r0 = cta * ROWS_PER_CTA;
    int r1 = r0 + ROWS_PER_CTA; if (r1 > N_NODES) r1 = N_NODES;
    const int nrows = r1 - r0;
    const int kbase = r0 * CHUNKS;
    const int nk    = nrows * CHUNKS;             // <= 1352
    unsigned bar = 0;

    unsigned int sv_u32;
    asm("{ .reg .u64 t; cvta.to.shared.u64 t, %1; cvt.u32.u64 %0, t; }"
        : "=r"(sv_u32) : "l"(sv));

    // ---- phase A: zero this chunk's key counters + rowsum v0 ----
    for (int i = kbase + tid; i < kbase + nk; i += T_P) g_cnt[i] = 0;
    for (int n = r0 + wid; n < r1; n += 32) {
        const float4* xr = reinterpret_cast<const float4*>(x + (size_t)n * F_IN);
        float4 v = __ldg(&xr[lane]);
        float s = v.x + v.y + v.z + v.w;
        #pragma unroll
        for (int o = 16; o; o >>= 1) s += __shfl_xor_sync(0xffffffffu, s, o);
        if (lane == 0) g_s[n] = s;
    }
    grid_barrier(++bar);

    // ---- phase B: histogram over (row, col-chunk) keys, int4-vectorized ----
    {
        const int4* rows4 = reinterpret_cast<const int4*>(rows);
        const int4* cols4 = reinterpret_cast<const int4*>(cols);
        const int total4 = N_EDGES / 4;
        for (int i = cta * T_P + tid; i < total4; i += GRID_P * T_P) {
            int4 r = __ldg(&rows4[i]);
            int4 c = __ldg(&cols4[i]);
            atomicAdd(&g_cnt[r.x * CHUNKS + c.x / CHUNK_N], 1);
            atomicAdd(&g_cnt[r.y * CHUNKS + c.y / CHUNK_N], 1);
            atomicAdd(&g_cnt[r.z * CHUNKS + c.z / CHUNK_N], 1);
            atomicAdd(&g_cnt[r.w * CHUNKS + c.w / CHUNK_N], 1);
        }
    }
    grid_barrier(++bar);

    // ---- phase C1: block-local scan of this CTA's key counts (2 keys/thread) ----
    int c0 = 0, c1 = 0;
    {
        int t2 = tid * 2;
        if (t2     < nk) c0 = g_cnt[kbase + t2];
        if (t2 + 1 < nk) c1 = g_cnt[kbase + t2 + 1];
        scanbuf[tid] = c0 + c1;
    }
    __syncthreads();
    #pragma unroll
    for (int off = 1; off < T_P; off <<= 1) {
        int v = (tid >= off) ? scanbuf[tid - off] : 0;
        __syncthreads();
        scanbuf[tid] += v;
        __syncthreads();
    }
    if (tid == 0) g_part[cta] = scanbuf[T_P - 1];
    grid_barrier(++bar);

    // ---- phase C2: prefix of partials -> rowptr + fill cursors ----
    if (tid == 0) {
        int b = 0;
        #pragma unroll 4
        for (int i = 0; i < cta; i++) b += g_part[i];
        s_base = b;
        if (cta == 0) g_rowptr[NKEYS] = N_EDGES;
    }
    __syncthreads();
    {
        int t2  = tid * 2;
        int pre = s_base + (tid ? scanbuf[tid - 1] : 0);   // exclusive pair prefix
        if (t2 < nk) {
            g_rowptr[kbase + t2] = pre;
            g_fill  [kbase + t2] = pre;
        }
        if (t2 + 1 < nk) {
            g_rowptr[kbase + t2 + 1] = pre + c0;
            g_fill  [kbase + t2 + 1] = pre + c0;
        }
    }
    grid_barrier(++bar);

    // ---- phase D: scatter edges into chunked-CSR slots (float4/int4 reads) ----
    {
        const int4*   rows4 = reinterpret_cast<const int4*>(rows);
        const int4*   cols4 = reinterpret_cast<const int4*>(cols);
        const float4* vals4 = reinterpret_cast<const float4*>(vals);
        const int total4 = N_EDGES / 4;
        for (int i = cta * T_P + tid; i < total4; i += GRID_P * T_P) {
            int4   r = __ldg(&rows4[i]);
            int4   c = __ldg(&cols4[i]);
            float4 v = __ldg(&vals4[i]);
            int p0 = atomicAdd(&g_fill[r.x * CHUNKS + c.x / CHUNK_N], 1);
            int p1 = atomicAdd(&g_fill[r.y * CHUNKS + c.y / CHUNK_N], 1);
            int p2 = atomicAdd(&g_fill[r.z * CHUNKS + c.z / CHUNK_N], 1);
            int p3 = atomicAdd(&g_fill[r.w * CHUNKS + c.w / CHUNK_N], 1);
            g_csr[p0] = make_int2(c.x, __float_as_int(v.x));
            g_csr[p1] = make_int2(c.y, __float_as_int(v.y));
            g_csr[p2] = make_int2(c.z, __float_as_int(v.z));
            g_csr[p3] = make_int2(c.w, __float_as_int(v.w));
        }
    }
    grid_barrier(++bar);

    // ---- phase E: 25 power iterations, fill pipelined over 4 column chunks ----
    for (int p = 1; p <= MAX_POWER; p++) {
        const float4* vin4 = reinterpret_cast<const float4*>(g_s + (size_t)(p - 1) * N_NODES);

        // issue all 4 chunk copies as separate commit groups (async DMA)
        #pragma unroll
        for (int c = 0; c < CHUNKS; c++) {
            const float4* src = vin4 + c * CF4;
            unsigned int  dst = sv_u32 + (unsigned int)(c * CF4) * 16u;
            for (int i = tid; i < CF4; i += T_P)
                cp_async16(dst + (unsigned int)i * 16u, src + i);
            cp_commit();
        }

        float* __restrict__ vout = g_s + (size_t)p * N_NODES;

        // process chunk c: gather from sv[chunk-c cols], accumulate per row.
        // same (sl==0) thread touches racc[row] across all chunks: race-free.
        #define GFL_CHUNK_BODY(CC)                                              \
        {                                                                       \
            CP_WAIT_GROUP(CHUNKS - 1 - (CC));     /* chunks 0..CC landed */     \
            __syncthreads();                      /* ...for every thread */     \
            for (int row = r0 + wid * 4 + sub; row < r1; row += 32 * 4) {       \
                int beg = __ldg(&g_rowptr[row * CHUNKS + (CC)]);                \
                int end = __ldg(&g_rowptr[row * CHUNKS + (CC) + 1]);            \
                float acc = 0.0f;                                               \
                for (int i = beg + sl; i < end; i += 8) {                       \
                    int2 e = __ldg(&g_csr[i]);                                  \
                    acc += __int_as_float(e.y) * sv[e.x];                       \
                }                                                               \
                acc += __shfl_xor_sync(submask, acc, 4);                        \
                acc += __shfl_xor_sync(submask, acc, 2);                        \
                acc += __shfl_xor_sync(submask, acc, 1);                        \
                if (sl == 0) {                                                  \
                    if ((CC) == 0)               racc[row - r0]  = acc;         \
                    else if ((CC) < CHUNKS - 1)  racc[row - r0] += acc;         \
                    else                         vout[row] = racc[row - r0] + acc; \
                }                                                               \
            }                                                                   \
        }
        GFL_CHUNK_BODY(0)
        GFL_CHUNK_BODY(1)
        GFL_CHUNK_BODY(2)
        GFL_CHUNK_BODY(3)
        #undef GFL_CHUNK_BODY

        grid_barrier(++bar);
    }

    // ---- phase F: y[n,o] = sum_k coeff[o,k] * s[1 + o*(K-1) + k][n] ----
    for (int n = r0 + tid; n < r1; n += T_P) {
        float svv[MAX_POWER];
        #pragma unroll
        for (int p = 0; p < MAX_POWER; p++)
            svv[p] = g_s[(size_t)(p + 1) * N_NODES + n];
        #pragma unroll
        for (int o = 0; o < F_OUT; o++) {
            float acc = 0.0f;
            #pragma unroll
            for (int k = 0; k < K_TAPS; k++)
                acc += __ldg(&coeff[o * K_TAPS + k]) * svv[o * (K_TAPS - 1) + k];
            y[(size_t)n * F_OUT + o] = acc;
        }
    }

    // ---- reset barrier state for next launch/replay (last finisher) ----
    __syncthreads();
    if (tid == 0) {
        __threadfence();
        unsigned old = atomicAdd(&g_done, 1u);
        if (old == GRID_P - 1) {
            g_arrive = 0u;
            g_epoch  = 0u;
            g_done   = 0u;
            __threadfence();
        }
    }
}

// ---------------------------------------------------------------------------
extern "C" void kernel_launch(void* const* d_in, const int* in_sizes, int n_in,
                              void* d_out, int out_size) {
    const float* x     = (const float*)d_in[0];
    const int*   rows  = (const int*)  d_in[1];
    const int*   cols  = (const int*)  d_in[2];
    const float* vals  = (const float*)d_in[3];
    const float* coeff = (const float*)d_in[4];
    float*       y     = (float*)d_out;

    cudaFuncSetAttribute(gfl_fused_kernel,
                         cudaFuncAttributeMaxDynamicSharedMemorySize, SMEM_BYTES);

    gfl_fused_kernel<<<GRID_P, T_P, SMEM_BYTES>>>(x, rows, cols, vals, coeff, y);
}

// round 16
// speedup vs baseline: 1.7100x; 1.7100x over previous
#include <cuda_runtime.h>
#include <cuda_bf16.h>
#include <cstdint>

#define N_NODES   50000
#define N_EDGES   1600000
#define F_IN      128
#define F_OUT     8
#define K_TAPS    4
#define MAX_POWER 25            // F_OUT*(K_TAPS-1)+1

#define CHUNKS      2
#define CHUNK_N     (N_NODES / CHUNKS)      // 25000 nodes per column chunk
#define CHUNK_BYTES (CHUNK_N * 4)           // 100000 B (16B-multiple)
#define NKEYS       (N_NODES * CHUNKS)      // 100000 (row, chunk) keys

#define GRID_P    148           // persistent grid: 1 CTA/SM, all co-resident
#define T_P       1024
#define ROWS_PER_CTA ((N_NODES + GRID_P - 1) / GRID_P)   // 338
#define SMEM_BYTES (N_NODES * 4)                          // 200 KB dynamic

// ---- device-global scratch ----
__device__ __align__(16) float g_s[(MAX_POWER + 1) * N_NODES];  // 5.2 MB
__device__ int      g_cnt[NKEYS];
__device__ int      g_rowptr[NKEYS + 1];
__device__ int      g_fill[NKEYS];
__device__ int2     g_csr[N_EDGES];                   // packed {col, val-bits}
__device__ int      g_part[GRID_P];                   // per-CTA edge-count partials
__device__ unsigned g_arrive;                         // barrier arrivals (monotonic)
__device__ unsigned g_epoch;                          // completed-epoch counter
__device__ unsigned g_done;                           // end-of-kernel reset counter

// ---------------------------------------------------------------------------
// mbarrier + TMA bulk-copy helpers
// ---------------------------------------------------------------------------
__device__ __forceinline__ unsigned smem_u32(const void* p) {
    return (unsigned)__cvta_generic_to_shared(p);
}
__device__ __forceinline__ void mbar_init(unsigned mbar, unsigned count) {
    asm volatile("mbarrier.init.shared.b64 [%0], %1;" :: "r"(mbar), "r"(count) : "memory");
}
__device__ __forceinline__ void mbar_expect_tx(unsigned mbar, unsigned bytes) {
    asm volatile("mbarrier.arrive.expect_tx.shared.b64 _, [%0], %1;"
                 :: "r"(mbar), "r"(bytes) : "memory");
}
__device__ __forceinline__ void tma_bulk_g2s(unsigned dst_smem, const void* src,
                                             unsigned bytes, unsigned mbar) {
    asm volatile("cp.async.bulk.shared::cta.global.mbarrier::complete_tx::bytes "
                 "[%0], [%1], %2, [%3];"
                 :: "r"(dst_smem), "l"(src), "r"(bytes), "r"(mbar) : "memory");
}
__device__ __forceinline__ void mbar_wait(unsigned mbar, unsigned parity) {
    asm volatile(
        "{\n\t"
        ".reg .pred P;\n\t"
        "WAIT_%=:\n\t"
        "mbarrier.try_wait.parity.acquire.cta.shared::cta.b64 P, [%0], %1, 0x989680;\n\t"
        "@P bra.uni DONE_%=;\n\t"
        "bra.uni WAIT_%=;\n\t"
        "DONE_%=:\n\t"
        "}"
        :: "r"(mbar), "r"(parity) : "memory");
}

// ---------------------------------------------------------------------------
// Device-wide barrier: one atomic arrive per CTA; LAST arriver publishes the
// epoch; everyone else spins on a PLAIN LOAD with nanosleep backoff.
// ---------------------------------------------------------------------------
__device__ __forceinline__ void grid_barrier(unsigned target) {
    __syncthreads();
    if (threadIdx.x == 0) {
        __threadfence();                               // release this CTA's writes
        unsigned arrived = atomicAdd(&g_arrive, 1u) + 1u;
        if (arrived == target * GRID_P) {
            __threadfence();
            *(volatile unsigned*)&g_epoch = target;    // publish epoch
        } else {
            while (*(volatile unsigned*)&g_epoch < target) __nanosleep(32);
        }
        __threadfence();                               // acquire
    }
    __syncthreads();
}

// ---------------------------------------------------------------------------
// ONE fused persistent kernel: 2-chunk CSR build + rowsum + 25 TMA-pipelined
// power iterations + output. smem holds the whole power vector (200 KB).
// ---------------------------------------------------------------------------
__global__ void __launch_bounds__(T_P, 1)
gfl_fused_kernel(const float* __restrict__ x,
                 const int*   __restrict__ rows,
                 const int*   __restrict__ cols,
                 const float* __restrict__ vals,
                 const float* __restrict__ coeff,
                 float*       __restrict__ y) {
    extern __shared__ float sv[];                 // N_NODES floats (dynamic)
    __shared__ int   scanbuf[T_P];
    __shared__ float racc[ROWS_PER_CTA];
    __shared__ int   s_base;
    __shared__ __align__(8) unsigned long long s_mbar[2];

    const int tid  = threadIdx.x;
    const int wid  = tid >> 5;
    const int lane = tid & 31;
    const int sub  = lane >> 3;                   // 8-lane sub-group 0..3
    const int sl   = lane & 7;
    const unsigned submask = 0xFFu << (sub * 8);
    const int cta  = blockIdx.x;

    const int r0 = cta * ROWS_PER_CTA;
    int r1 = r0 + ROWS_PER_CTA; if (r1 > N_NODES) r1 = N_NODES;
    const int nrows = r1 - r0;
    const int kbase = r0 * CHUNKS;
    const int nk    = nrows * CHUNKS;             // <= 676 (fits 1 key/thread)
    unsigned bar = 0;

    const unsigned sv_u32 = smem_u32(sv);
    const unsigned mb0 = smem_u32(&s_mbar[0]);
    const unsigned mb1 = smem_u32(&s_mbar[1]);
    if (tid == 0) { mbar_init(mb0, 1); mbar_init(mb1, 1); }
    // (first use is after grid_barrier(1): init is globally visible by then)

    // ---- phase A: zero this CTA's key counters + rowsum v0 ----
    for (int i = kbase + tid; i < kbase + nk; i += T_P) g_cnt[i] = 0;
    for (int n = r0 + wid; n < r1; n += 32) {
        const float4* xr = reinterpret_cast<const float4*>(x + (size_t)n * F_IN);
        float4 v = __ldg(&xr[lane]);
        float s = v.x + v.y + v.z + v.w;
        #pragma unroll
        for (int o = 16; o; o >>= 1) s += __shfl_xor_sync(0xffffffffu, s, o);
        if (lane == 0) g_s[n] = s;
    }
    grid_barrier(++bar);

    // ---- phase B: histogram over (row, col-chunk) keys, int4-vectorized ----
    {
        const int4* rows4 = reinterpret_cast<const int4*>(rows);
        const int4* cols4 = reinterpret_cast<const int4*>(cols);
        const int total4 = N_EDGES / 4;
        for (int i = cta * T_P + tid; i < total4; i += GRID_P * T_P) {
            int4 r = __ldg(&rows4[i]);
            int4 c = __ldg(&cols4[i]);
            atomicAdd(&g_cnt[r.x * CHUNKS + (c.x >= CHUNK_N)], 1);
            atomicAdd(&g_cnt[r.y * CHUNKS + (c.y >= CHUNK_N)], 1);
            atomicAdd(&g_cnt[r.z * CHUNKS + (c.z >= CHUNK_N)], 1);
            atomicAdd(&g_cnt[r.w * CHUNKS + (c.w >= CHUNK_N)], 1);
        }
    }
    grid_barrier(++bar);

    // ---- phase C1: block-local scan of this CTA's key counts (1 key/thread) ----
    {
        int c0 = (tid < nk) ? g_cnt[kbase + tid] : 0;
        scanbuf[tid] = c0;
    }
    __syncthreads();
    #pragma unroll
    for (int off = 1; off < T_P; off <<= 1) {
        int v = (tid >= off) ? scanbuf[tid - off] : 0;
        __syncthreads();
        scanbuf[tid] += v;
        __syncthreads();
    }
    if (tid == 0) g_part[cta] = scanbuf[T_P - 1];
    grid_barrier(++bar);

    // ---- phase C2: prefix of partials -> rowptr + fill cursors ----
    if (tid == 0) {
        int b = 0;
        #pragma unroll 4
        for (int i = 0; i < cta; i++) b += g_part[i];
        s_base = b;
        if (cta == 0) g_rowptr[NKEYS] = N_EDGES;
    }
    __syncthreads();
    if (tid < nk) {
        int pre = s_base + (tid ? scanbuf[tid - 1] : 0);   // exclusive prefix
        g_rowptr[kbase + tid] = pre;
        g_fill  [kbase + tid] = pre;
    }
    grid_barrier(++bar);

    // ---- phase D: scatter edges into chunked-CSR slots (int4/float4 reads) ----
    {
        const int4*   rows4 = reinterpret_cast<const int4*>(rows);
        const int4*   cols4 = reinterpret_cast<const int4*>(cols);
        const float4* vals4 = reinterpret_cast<const float4*>(vals);
        const int total4 = N_EDGES / 4;
        for (int i = cta * T_P + tid; i < total4; i += GRID_P * T_P) {
            int4   r = __ldg(&rows4[i]);
            int4   c = __ldg(&cols4[i]);
            float4 v = __ldg(&vals4[i]);
            int p0 = atomicAdd(&g_fill[r.x * CHUNKS + (c.x >= CHUNK_N)], 1);
            int p1 = atomicAdd(&g_fill[r.y * CHUNKS + (c.y >= CHUNK_N)], 1);
            int p2 = atomicAdd(&g_fill[r.z * CHUNKS + (c.z >= CHUNK_N)], 1);
            int p3 = atomicAdd(&g_fill[r.w * CHUNKS + (c.w >= CHUNK_N)], 1);
            g_csr[p0] = make_int2(c.x, __float_as_int(v.x));
            g_csr[p1] = make_int2(c.y, __float_as_int(v.y));
            g_csr[p2] = make_int2(c.z, __float_as_int(v.z));
            g_csr[p3] = make_int2(c.w, __float_as_int(v.w));
        }
    }
    grid_barrier(++bar);

    // ---- phase E: 25 power iterations; fill via TMA bulk copy, 2 chunks ----
    for (int p = 1; p <= MAX_POWER; p++) {
        const float*   vin = g_s + (size_t)(p - 1) * N_NODES;
        float* __restrict__ vout = g_s + (size_t)p * N_NODES;
        const unsigned ph  = (unsigned)((p - 1) & 1);

        if (tid == 0) {
            mbar_expect_tx(mb0, CHUNK_BYTES);
            tma_bulk_g2s(sv_u32, vin, CHUNK_BYTES, mb0);
            mbar_expect_tx(mb1, CHUNK_BYTES);
            tma_bulk_g2s(sv_u32 + CHUNK_BYTES, vin + CHUNK_N, CHUNK_BYTES, mb1);
        }

        // chunk 0: partial row sums into racc (same thread writes/reads)
        mbar_wait(mb0, ph);
        for (int row = r0 + wid * 4 + sub; row < r1; row += 32 * 4) {
            int beg = __ldg(&g_rowptr[row * CHUNKS]);
            int end = __ldg(&g_rowptr[row * CHUNKS + 1]);
            float acc = 0.0f;
            for (int i = beg + sl; i < end; i += 8) {
                int2 e = __ldg(&g_csr[i]);
                acc += __int_as_float(e.y) * sv[e.x];
            }
            acc += __shfl_xor_sync(submask, acc, 4);
            acc += __shfl_xor_sync(submask, acc, 2);
            acc += __shfl_xor_sync(submask, acc, 1);
            if (sl == 0) racc[row - r0] = acc;
        }

        // chunk 1: finish and write vout
        mbar_wait(mb1, ph);
        for (int row = r0 + wid * 4 + sub; row < r1; row += 32 * 4) {
            int beg = __ldg(&g_rowptr[row * CHUNKS + 1]);
            int end = __ldg(&g_rowptr[row * CHUNKS + 2]);
            float acc = 0.0f;
            for (int i = beg + sl; i < end; i += 8) {
                int2 e = __ldg(&g_csr[i]);
                acc += __int_as_float(e.y) * sv[e.x];
            }
            acc += __shfl_xor_sync(submask, acc, 4);
            acc += __shfl_xor_sync(submask, acc, 2);
            acc += __shfl_xor_sync(submask, acc, 1);
            if (sl == 0) vout[row] = racc[row - r0] + acc;
        }

        grid_barrier(++bar);    // includes __syncthreads: safe to re-arm mbarriers
    }

    // ---- phase F: y[n,o] = sum_k coeff[o,k] * s[1 + o*(K-1) + k][n] ----
    for (int n = r0 + tid; n < r1; n += T_P) {
        float svv[MAX_POWER];
        #pragma unroll
        for (int p = 0; p < MAX_POWER; p++)
            svv[p] = g_s[(size_t)(p + 1) * N_NODES + n];
        #pragma unroll
        for (int o = 0; o < F_OUT; o++) {
            float acc = 0.0f;
            #pragma unroll
            for (int k = 0; k < K_TAPS; k++)
                acc += __ldg(&coeff[o * K_TAPS + k]) * svv[o * (K_TAPS - 1) + k];
            y[(size_t)n * F_OUT + o] = acc;
        }
    }

    // ---- reset barrier state for next launch/replay (last finisher) ----
    __syncthreads();
    if (tid == 0) {
        __threadfence();
        unsigned old = atomicAdd(&g_done, 1u);
        if (old == GRID_P - 1) {
            g_arrive = 0u;
            g_epoch  = 0u;
            g_done   = 0u;
            __threadfence();
        }
    }
}

// ---------------------------------------------------------------------------
extern "C" void kernel_launch(void* const* d_in, const int* in_sizes, int n_in,
                              void* d_out, int out_size) {
    const float* x     = (const float*)d_in[0];
    const int*   rows  = (const int*)  d_in[1];
    const int*   cols  = (const int*)  d_in[2];
    const float* vals  = (const float*)d_in[3];
    const float* coeff = (const float*)d_in[4];
    float*       y     = (float*)d_out;

    cudaFuncSetAttribute(gfl_fused_kernel,
                         cudaFuncAttributeMaxDynamicSharedMemorySize, SMEM_BYTES);

    gfl_fused_kernel<<<GRID_P, T_P, SMEM_BYTES>>>(x, rows, cols, vals, coeff, y);
}